// round 14
// baseline (speedup 1.0000x reference)
#include <cuda_runtime.h>
#include <cuda_fp16.h>
#include <math.h>

#define NROW   100000
#define IN_CH  128
#define OUT_CH 40
#define NED    3200000
#define NBLK   ((NROW + 255) / 256)   // 391 scan blocks

// Scratch (static device globals; BSS-zeroed at load)
__device__ __half2 g_z0[NROW * 20];  // (xW)*dinv, fp16, 80 B/row (8 MB)
__device__ __half2 g_z1[NROW * 20];  // after hop 1, fp16 (8 MB)
__device__ float   g_dinv[NROW];
__device__ int     g_degi[NROW];     // edge-only in-degree; re-zeroed each run
__device__ int     g_cnt[NROW];      // stable copy of edge counts
__device__ int     g_start[NROW];    // CSC row starts
__device__ int     g_cursor[NROW];
__device__ int     g_srcs[NED];      // CSC source indices (12.8 MB)
__device__ int     g_perm[NROW];     // block-local degree-sorted node order
__device__ int     g_bsum[NBLK];

// ---------------------------------------------------------------------------
// count in-degree, 4 edges per thread (int4). g_degi zero on entry
// (BSS first call; k_finalize re-zeroes every run).
__global__ void k_count(const int* __restrict__ ei) {
    int t = blockIdx.x * blockDim.x + threadIdx.x;
    if (t >= NED / 4) return;
    int4 c4 = __ldg((const int4*)(ei + NED) + t);
    int c;
    c = c4.x; if ((unsigned)c >= NROW) c = 0; atomicAdd(&g_degi[c], 1);
    c = c4.y; if ((unsigned)c >= NROW) c = 0; atomicAdd(&g_degi[c], 1);
    c = c4.z; if ((unsigned)c >= NROW) c = 0; atomicAdd(&g_degi[c], 1);
    c = c4.w; if ((unsigned)c >= NROW) c = 0; atomicAdd(&g_degi[c], 1);
}

// ---------------------------------------------------------------------------
// Block scan over edge counts + block-local bitonic sort by degree -> g_perm.
__global__ void k_scan_nodes() {
    __shared__ int sh[256];
    __shared__ int skey[256];
    __shared__ int sval[256];
    int tid = threadIdx.x;
    int base = blockIdx.x * 256;
    int i = base + tid;
    int c = (i < NROW) ? g_degi[i] : 0;
    sh[tid] = c;
    skey[tid] = (i < NROW) ? c : 0x7FFFFFFF;   // sentinels sort last
    sval[tid] = tid;
    __syncthreads();
    #pragma unroll
    for (int off = 1; off < 256; off <<= 1) {
        int t2 = (tid >= off) ? sh[tid - off] : 0;
        __syncthreads();
        sh[tid] += t2;
        __syncthreads();
    }
    if (i < NROW) g_start[i] = sh[tid] - c;    // block-local exclusive
    if (tid == 255) g_bsum[blockIdx.x] = sh[255];

    // bitonic sort (ascending by key) of 256 (key,val) pairs
    for (int k = 2; k <= 256; k <<= 1) {
        for (int j = k >> 1; j > 0; j >>= 1) {
            __syncthreads();
            int ixj = tid ^ j;
            if (ixj > tid) {
                bool up = ((tid & k) == 0);
                int ka = skey[tid], kb = skey[ixj];
                if ((ka > kb) == up) {
                    int va = sval[tid], vb = sval[ixj];
                    skey[tid] = kb; skey[ixj] = ka;
                    sval[tid] = vb; sval[ixj] = va;
                }
            }
        }
    }
    __syncthreads();
    if (i < NROW) g_perm[i] = base + sval[tid];   // valid keys occupy low ranks
}

// finalize: block offset = reduce(bsum[0..bid)), offsets, cursors, dinv,
// counts snapshot, degi re-zero.
__global__ void k_finalize() {
    __shared__ int red[256];
    int bid = blockIdx.x;
    int tid = threadIdx.x;
    int s = 0;
    for (int j = tid; j < bid; j += 256) s += g_bsum[j];
    red[tid] = s;
    __syncthreads();
    #pragma unroll
    for (int off = 128; off > 0; off >>= 1) {
        if (tid < off) red[tid] += red[tid + off];
        __syncthreads();
    }
    int boff = red[0];

    int i = bid * 256 + tid;
    if (i < NROW) {
        int st = g_start[i] + boff;
        g_start[i]  = st;
        g_cursor[i] = st;
        int c = g_degi[i];
        g_cnt[i]  = c;
        g_dinv[i] = rsqrtf((float)(c + 1));   // deg incl. self-loop
        g_degi[i] = 0;                        // restore invariant for next run
    }
}

// ---------------------------------------------------------------------------
// Fused kernel: HMMA GEMM blocks + CSC-fill blocks (R10 winner, unchanged).
#define GEMM_BLOCKS 782                 // ceil(100000 / 128), 8 warps x 16 rows
#define FILL_BLOCKS 3125                // NED / (256*4)
#define FG_T        256
#define WSTRIDE     136                 // half-stride of transposed W (bank-safe)

__global__ __launch_bounds__(FG_T)
void k_fill_gemm(const float* __restrict__ x,
                 const float* __restrict__ W,
                 const int* __restrict__ ei) {
    __shared__ __half wsmT[OUT_CH * WSTRIDE];   // W^T fp16, [n][k], 10.9 KB

    if (blockIdx.x < GEMM_BLOCKS) {
        for (int i = threadIdx.x; i < IN_CH * OUT_CH; i += FG_T) {
            int k = i / OUT_CH, n = i % OUT_CH;
            wsmT[n * WSTRIDE + k] = __float2half_rn(W[i]);
        }
        __syncthreads();

        int warp = threadIdx.x >> 5, lane = threadIdx.x & 31;
        int r0 = (blockIdx.x * 8 + warp) * 16;
        if (r0 >= NROW) return;                  // 100000 % 16 == 0
        int qrow = lane >> 2;                    // 0..7
        int qcol = (lane & 3) * 2;               // 0,2,4,6

        float c[5][4];
        #pragma unroll
        for (int nt = 0; nt < 5; nt++)
            c[nt][0] = c[nt][1] = c[nt][2] = c[nt][3] = 0.f;

        const float* xr0 = x + (size_t)(r0 + qrow) * IN_CH + qcol;
        const float* xr8 = xr0 + 8 * IN_CH;

        #pragma unroll
        for (int ks = 0; ks < 8; ks++) {
            int k0 = ks * 16;
            float2 f0 = *(const float2*)(xr0 + k0);
            float2 f1 = *(const float2*)(xr8 + k0);
            float2 f2 = *(const float2*)(xr0 + k0 + 8);
            float2 f3 = *(const float2*)(xr8 + k0 + 8);
            __half2 h0 = __floats2half2_rn(f0.x, f0.y);
            __half2 h1 = __floats2half2_rn(f1.x, f1.y);
            __half2 h2 = __floats2half2_rn(f2.x, f2.y);
            __half2 h3 = __floats2half2_rn(f3.x, f3.y);
            unsigned A0 = *(unsigned*)&h0, A1 = *(unsigned*)&h1;
            unsigned A2 = *(unsigned*)&h2, A3 = *(unsigned*)&h3;

            #pragma unroll
            for (int nt = 0; nt < 5; nt++) {
                int n = nt * 8 + qrow;
                unsigned B0 = *(const unsigned*)&wsmT[n * WSTRIDE + k0 + qcol];
                unsigned B1 = *(const unsigned*)&wsmT[n * WSTRIDE + k0 + qcol + 8];
                asm volatile(
                    "mma.sync.aligned.m16n8k16.row.col.f32.f16.f16.f32 "
                    "{%0,%1,%2,%3}, {%4,%5,%6,%7}, {%8,%9}, {%0,%1,%2,%3};\n"
                    : "+f"(c[nt][0]), "+f"(c[nt][1]), "+f"(c[nt][2]), "+f"(c[nt][3])
                    : "r"(A0), "r"(A1), "r"(A2), "r"(A3), "r"(B0), "r"(B1));
            }
        }

        int row0 = r0 + qrow, row8 = row0 + 8;
        float d0 = g_dinv[row0], d8 = g_dinv[row8];
        #pragma unroll
        for (int nt = 0; nt < 5; nt++) {
            int cidx = nt * 4 + (qcol >> 1);
            g_z0[row0 * 20 + cidx] = __floats2half2_rn(c[nt][0] * d0, c[nt][1] * d0);
            g_z0[row8 * 20 + cidx] = __floats2half2_rn(c[nt][2] * d8, c[nt][3] * d8);
        }
    } else {
        // ---- CSC fill branch: 4 edges per thread ----
        int t = (blockIdx.x - GEMM_BLOCKS) * FG_T + threadIdx.x;
        if (t >= NED / 4) return;
        int4 r4 = __ldg((const int4*)ei + t);
        int4 c4 = __ldg((const int4*)(ei + NED) + t);
        int r, c, slot;
        r = r4.x; c = c4.x;
        if ((unsigned)r >= NROW) r = 0;
        if ((unsigned)c >= NROW) c = 0;
        slot = atomicAdd(&g_cursor[c], 1); g_srcs[slot] = r;
        r = r4.y; c = c4.y;
        if ((unsigned)r >= NROW) r = 0;
        if ((unsigned)c >= NROW) c = 0;
        slot = atomicAdd(&g_cursor[c], 1); g_srcs[slot] = r;
        r = r4.z; c = c4.z;
        if ((unsigned)r >= NROW) r = 0;
        if ((unsigned)c >= NROW) c = 0;
        slot = atomicAdd(&g_cursor[c], 1); g_srcs[slot] = r;
        r = r4.w; c = c4.w;
        if ((unsigned)r >= NROW) r = 0;
        if ((unsigned)c >= NROW) c = 0;
        slot = atomicAdd(&g_cursor[c], 1); g_srcs[slot] = r;
    }
}

// ---------------------------------------------------------------------------
// fp16 gather core: thread = (node, chunk c in 0..4), chunk = 8 channels.
__device__ __forceinline__ void hacc(float* a, uint4 v) {
    float2 f;
    f = __half22float2(*(__half2*)&v.x); a[0] += f.x; a[1] += f.y;
    f = __half22float2(*(__half2*)&v.y); a[2] += f.x; a[3] += f.y;
    f = __half22float2(*(__half2*)&v.z); a[4] += f.x; a[5] += f.y;
    f = __half22float2(*(__half2*)&v.w); a[6] += f.x; a[7] += f.y;
}

__device__ __forceinline__ void gather8(float* acc, int node, int c,
                                        const __half2* __restrict__ src) {
    const uint4* base = (const uint4*)src;     // 5 uint4 per row
    float b[8];
    #pragma unroll
    for (int j = 0; j < 8; j++) { acc[j] = 0.f; b[j] = 0.f; }

    uint4 self = __ldg(base + node * 5 + c);
    hacc(acc, self);

    int s0  = g_start[node];
    int cnt = g_cnt[node];                     // edge-only count
    int k = 0;
    for (; k + 8 <= cnt; k += 8) {
        int i0 = g_srcs[s0 + k + 0];
        int i1 = g_srcs[s0 + k + 1];
        int i2 = g_srcs[s0 + k + 2];
        int i3 = g_srcs[s0 + k + 3];
        int i4 = g_srcs[s0 + k + 4];
        int i5 = g_srcs[s0 + k + 5];
        int i6 = g_srcs[s0 + k + 6];
        int i7 = g_srcs[s0 + k + 7];
        uint4 v0 = __ldg(base + i0 * 5 + c);
        uint4 v1 = __ldg(base + i1 * 5 + c);
        uint4 v2 = __ldg(base + i2 * 5 + c);
        uint4 v3 = __ldg(base + i3 * 5 + c);
        uint4 v4 = __ldg(base + i4 * 5 + c);
        uint4 v5 = __ldg(base + i5 * 5 + c);
        uint4 v6 = __ldg(base + i6 * 5 + c);
        uint4 v7 = __ldg(base + i7 * 5 + c);
        hacc(acc, v0); hacc(b, v1); hacc(acc, v2); hacc(b, v3);
        hacc(acc, v4); hacc(b, v5); hacc(acc, v6); hacc(b, v7);
    }
    for (; k < cnt; k++) {
        int i0 = g_srcs[s0 + k];
        hacc(acc, __ldg(base + i0 * 5 + c));
    }
    #pragma unroll
    for (int j = 0; j < 8; j++) acc[j] += b[j];
}

// hop 1: z1 = dinv^2 * gather(z0), fp16 out. 320 thr = 64 perm-nodes x 5 chunks.
__global__ __launch_bounds__(320) void k_gather1() {
    int t = threadIdx.x;
    int r = t / 5, c = t % 5;
    int idx = blockIdx.x * 64 + r;
    if (idx >= NROW) return;
    int node = g_perm[idx];                    // warp's nodes have similar degree
    float acc[8];
    gather8(acc, node, c, g_z0);
    float d = g_dinv[node];
    float s = d * d;
    uint4 o;
    *(__half2*)&o.x = __floats2half2_rn(acc[0] * s, acc[1] * s);
    *(__half2*)&o.y = __floats2half2_rn(acc[2] * s, acc[3] * s);
    *(__half2*)&o.z = __floats2half2_rn(acc[4] * s, acc[5] * s);
    *(__half2*)&o.w = __floats2half2_rn(acc[6] * s, acc[7] * s);
    ((uint4*)g_z1)[node * 5 + c] = o;
}

// hop 2 fused with bias + log_softmax. 320 thr = 64 perm-nodes x 5 chunks.
__global__ __launch_bounds__(320) void k_gather2_lsm(float* __restrict__ out,
                                                     const float* __restrict__ bias) {
    __shared__ float vals[64 * 41];
    __shared__ float lse[64];
    __shared__ int   nodes[64];
    int t = threadIdx.x;
    int r = t / 5, c = t % 5;
    int idx = blockIdx.x * 64 + r;
    bool active = (idx < NROW);
    int node = -1;

    if (active) {
        node = g_perm[idx];
        if (c == 0) nodes[r] = node;
        float acc[8];
        gather8(acc, node, c, g_z1);
        float d = g_dinv[node];
        #pragma unroll
        for (int j = 0; j < 8; j++)
            vals[r * 41 + c * 8 + j] = acc[j] * d + __ldg(&bias[c * 8 + j]);
    }
    __syncthreads();

    if (t < 64 && blockIdx.x * 64 + t < NROW) {
        const float* v = vals + t * 41;
        float m = v[0];
        #pragma unroll
        for (int j = 1; j < OUT_CH; j++) m = fmaxf(m, v[j]);
        float s = 0.f;
        #pragma unroll
        for (int j = 0; j < OUT_CH; j++) s += __expf(v[j] - m);
        lse[t] = m + __logf(s);
    }
    __syncthreads();

    if (active) {
        float l = lse[r];
        float4 o0, o1;
        const float* v = vals + r * 41 + c * 8;
        o0.x = v[0] - l; o0.y = v[1] - l; o0.z = v[2] - l; o0.w = v[3] - l;
        o1.x = v[4] - l; o1.y = v[5] - l; o1.z = v[6] - l; o1.w = v[7] - l;
        float4* op = (float4*)(out + (size_t)node * OUT_CH + c * 8);
        op[0] = o0; op[1] = o1;
    }
}

// ---------------------------------------------------------------------------
extern "C" void kernel_launch(void* const* d_in, const int* in_sizes, int n_in,
                              void* d_out, int out_size) {
    const float* x  = (const float*)d_in[0];
    const int*   ei = (const int*)d_in[1];    // int32 (JAX default x64 disabled)
    const float* W  = (const float*)d_in[2];
    const float* b  = (const float*)d_in[3];
    float*       out = (float*)d_out;

    const int T = 256;
    const int gC = (NED / 4 + T - 1) / T;            // 3125
    const int gP = (NROW + 63) / 64;                 // 1563 (64 nodes/block)

    k_count      <<<gC, T>>>(ei);
    k_scan_nodes <<<NBLK, 256>>>();
    k_finalize   <<<NBLK, 256>>>();
    k_fill_gemm  <<<GEMM_BLOCKS + FILL_BLOCKS, FG_T>>>(x, W, ei);
    k_gather1    <<<gP, 320>>>();
    k_gather2_lsm<<<gP, 320>>>(out, b);
}

// round 15
// speedup vs baseline: 1.0152x; 1.0152x over previous
#include <cuda_runtime.h>
#include <cuda_fp16.h>
#include <math.h>

#define NROW   100000
#define IN_CH  128
#define OUT_CH 40
#define NED    3200000
#define NBLK   ((NROW + 255) / 256)   // 391 scan blocks

// Scratch (static device globals; BSS-zeroed at load)
__device__ __half2 g_z0[NROW * 20];  // (xW)*dinv, fp16, 80 B/row (8 MB)
__device__ __half2 g_z1[NROW * 20];  // after hop 1, fp16 (8 MB)
__device__ float   g_dinv[NROW];
__device__ int     g_degi[NROW];     // edge-only in-degree; re-zeroed each run
__device__ int     g_cnt[NROW];      // stable copy of edge counts
__device__ int     g_start[NROW];    // CSC row starts
__device__ int     g_cursor[NROW];
__device__ int     g_srcs[NED];      // CSC source indices (12.8 MB)
__device__ int     g_bsum[NBLK];

// ---------------------------------------------------------------------------
// count in-degree, 8 edges per thread (2x int4). g_degi zero on entry
// (BSS first call; k_finalize re-zeroes every run).
__global__ void k_count(const int* __restrict__ ei) {
    int t = blockIdx.x * blockDim.x + threadIdx.x;
    if (t >= NED / 8) return;
    int4 ca = __ldg((const int4*)(ei + NED) + 2 * t);
    int4 cb = __ldg((const int4*)(ei + NED) + 2 * t + 1);
    int cc[8] = {ca.x, ca.y, ca.z, ca.w, cb.x, cb.y, cb.z, cb.w};
    #pragma unroll
    for (int j = 0; j < 8; j++) {
        int c = cc[j];
        if ((unsigned)c >= NROW) c = 0;
        atomicAdd(&g_degi[c], 1);
    }
}

// ---------------------------------------------------------------------------
// Block-level exclusive scan over edge counts; per-block totals to g_bsum.
__global__ void k_scan_nodes() {
    __shared__ int sh[256];
    int tid = threadIdx.x;
    int i = blockIdx.x * 256 + tid;
    int c = (i < NROW) ? g_degi[i] : 0;
    sh[tid] = c;
    __syncthreads();
    #pragma unroll
    for (int off = 1; off < 256; off <<= 1) {
        int t = (tid >= off) ? sh[tid - off] : 0;
        __syncthreads();
        sh[tid] += t;
        __syncthreads();
    }
    if (i < NROW) g_start[i] = sh[tid] - c;
    if (tid == 255) g_bsum[blockIdx.x] = sh[tid];
}

// finalize: block offset = reduce(bsum[0..bid)), offsets, cursors, dinv,
// counts snapshot, degi re-zero.
__global__ void k_finalize() {
    __shared__ int red[256];
    int bid = blockIdx.x;
    int tid = threadIdx.x;
    int s = 0;
    for (int j = tid; j < bid; j += 256) s += g_bsum[j];
    red[tid] = s;
    __syncthreads();
    #pragma unroll
    for (int off = 128; off > 0; off >>= 1) {
        if (tid < off) red[tid] += red[tid + off];
        __syncthreads();
    }
    int boff = red[0];

    int i = bid * 256 + tid;
    if (i < NROW) {
        int st = g_start[i] + boff;
        g_start[i]  = st;
        g_cursor[i] = st;
        int c = g_degi[i];
        g_cnt[i]  = c;
        g_dinv[i] = rsqrtf((float)(c + 1));   // deg incl. self-loop
        g_degi[i] = 0;                        // restore invariant for next run
    }
}

// ---------------------------------------------------------------------------
// Fused kernel: HMMA GEMM blocks + CSC-fill blocks (8 edges/thread).
#define GEMM_BLOCKS 782                 // ceil(100000 / 128), 8 warps x 16 rows
#define FILL_BLOCKS 1563                // ceil(NED / (256*8))
#define FG_T        256
#define WSTRIDE     136                 // half-stride of transposed W (bank-safe)

__global__ __launch_bounds__(FG_T)
void k_fill_gemm(const float* __restrict__ x,
                 const float* __restrict__ W,
                 const int* __restrict__ ei) {
    __shared__ __half wsmT[OUT_CH * WSTRIDE];   // W^T fp16, [n][k], 10.9 KB

    if (blockIdx.x < GEMM_BLOCKS) {
        for (int i = threadIdx.x; i < IN_CH * OUT_CH; i += FG_T) {
            int k = i / OUT_CH, n = i % OUT_CH;
            wsmT[n * WSTRIDE + k] = __float2half_rn(W[i]);
        }
        __syncthreads();

        int warp = threadIdx.x >> 5, lane = threadIdx.x & 31;
        int r0 = (blockIdx.x * 8 + warp) * 16;
        if (r0 >= NROW) return;                  // 100000 % 16 == 0
        int qrow = lane >> 2;                    // 0..7
        int qcol = (lane & 3) * 2;               // 0,2,4,6

        float c[5][4];
        #pragma unroll
        for (int nt = 0; nt < 5; nt++)
            c[nt][0] = c[nt][1] = c[nt][2] = c[nt][3] = 0.f;

        const float* xr0 = x + (size_t)(r0 + qrow) * IN_CH + qcol;
        const float* xr8 = xr0 + 8 * IN_CH;

        #pragma unroll
        for (int ks = 0; ks < 8; ks++) {
            int k0 = ks * 16;
            float2 f0 = *(const float2*)(xr0 + k0);
            float2 f1 = *(const float2*)(xr8 + k0);
            float2 f2 = *(const float2*)(xr0 + k0 + 8);
            float2 f3 = *(const float2*)(xr8 + k0 + 8);
            __half2 h0 = __floats2half2_rn(f0.x, f0.y);
            __half2 h1 = __floats2half2_rn(f1.x, f1.y);
            __half2 h2 = __floats2half2_rn(f2.x, f2.y);
            __half2 h3 = __floats2half2_rn(f3.x, f3.y);
            unsigned A0 = *(unsigned*)&h0, A1 = *(unsigned*)&h1;
            unsigned A2 = *(unsigned*)&h2, A3 = *(unsigned*)&h3;

            #pragma unroll
            for (int nt = 0; nt < 5; nt++) {
                int n = nt * 8 + qrow;
                unsigned B0 = *(const unsigned*)&wsmT[n * WSTRIDE + k0 + qcol];
                unsigned B1 = *(const unsigned*)&wsmT[n * WSTRIDE + k0 + qcol + 8];
                asm volatile(
                    "mma.sync.aligned.m16n8k16.row.col.f32.f16.f16.f32 "
                    "{%0,%1,%2,%3}, {%4,%5,%6,%7}, {%8,%9}, {%0,%1,%2,%3};\n"
                    : "+f"(c[nt][0]), "+f"(c[nt][1]), "+f"(c[nt][2]), "+f"(c[nt][3])
                    : "r"(A0), "r"(A1), "r"(A2), "r"(A3), "r"(B0), "r"(B1));
            }
        }

        int row0 = r0 + qrow, row8 = row0 + 8;
        float d0 = g_dinv[row0], d8 = g_dinv[row8];
        #pragma unroll
        for (int nt = 0; nt < 5; nt++) {
            int cidx = nt * 4 + (qcol >> 1);
            g_z0[row0 * 20 + cidx] = __floats2half2_rn(c[nt][0] * d0, c[nt][1] * d0);
            g_z0[row8 * 20 + cidx] = __floats2half2_rn(c[nt][2] * d8, c[nt][3] * d8);
        }
    } else {
        // ---- CSC fill branch: 8 edges per thread, all atomics in flight
        //      before the dependent scattered stores ----
        int t = (blockIdx.x - GEMM_BLOCKS) * FG_T + threadIdx.x;
        if (t >= NED / 8) return;
        int4 ra = __ldg((const int4*)ei + 2 * t);
        int4 rb = __ldg((const int4*)ei + 2 * t + 1);
        int4 ca = __ldg((const int4*)(ei + NED) + 2 * t);
        int4 cb = __ldg((const int4*)(ei + NED) + 2 * t + 1);

        int r[8] = {ra.x, ra.y, ra.z, ra.w, rb.x, rb.y, rb.z, rb.w};
        int c[8] = {ca.x, ca.y, ca.z, ca.w, cb.x, cb.y, cb.z, cb.w};
        #pragma unroll
        for (int j = 0; j < 8; j++) {
            if ((unsigned)r[j] >= NROW) r[j] = 0;
            if ((unsigned)c[j] >= NROW) c[j] = 0;
        }
        int slot[8];
        #pragma unroll
        for (int j = 0; j < 8; j++) slot[j] = atomicAdd(&g_cursor[c[j]], 1);
        #pragma unroll
        for (int j = 0; j < 8; j++) g_srcs[slot[j]] = r[j];
    }
}

// ---------------------------------------------------------------------------
// fp16 gather core: thread = (node, chunk c in 0..4), chunk = 8 channels.
__device__ __forceinline__ void hacc(float* a, uint4 v) {
    float2 f;
    f = __half22float2(*(__half2*)&v.x); a[0] += f.x; a[1] += f.y;
    f = __half22float2(*(__half2*)&v.y); a[2] += f.x; a[3] += f.y;
    f = __half22float2(*(__half2*)&v.z); a[4] += f.x; a[5] += f.y;
    f = __half22float2(*(__half2*)&v.w); a[6] += f.x; a[7] += f.y;
}

__device__ __forceinline__ void gather8(float* acc, int node, int c,
                                        const __half2* __restrict__ src) {
    const uint4* base = (const uint4*)src;     // 5 uint4 per row
    float b[8];
    #pragma unroll
    for (int j = 0; j < 8; j++) { acc[j] = 0.f; b[j] = 0.f; }

    uint4 self = __ldg(base + node * 5 + c);
    hacc(acc, self);

    int s0  = g_start[node];
    int cnt = g_cnt[node];                     // edge-only count
    int k = 0;
    for (; k + 8 <= cnt; k += 8) {
        int i0 = g_srcs[s0 + k + 0];
        int i1 = g_srcs[s0 + k + 1];
        int i2 = g_srcs[s0 + k + 2];
        int i3 = g_srcs[s0 + k + 3];
        int i4 = g_srcs[s0 + k + 4];
        int i5 = g_srcs[s0 + k + 5];
        int i6 = g_srcs[s0 + k + 6];
        int i7 = g_srcs[s0 + k + 7];
        uint4 v0 = __ldg(base + i0 * 5 + c);
        uint4 v1 = __ldg(base + i1 * 5 + c);
        uint4 v2 = __ldg(base + i2 * 5 + c);
        uint4 v3 = __ldg(base + i3 * 5 + c);
        uint4 v4 = __ldg(base + i4 * 5 + c);
        uint4 v5 = __ldg(base + i5 * 5 + c);
        uint4 v6 = __ldg(base + i6 * 5 + c);
        uint4 v7 = __ldg(base + i7 * 5 + c);
        hacc(acc, v0); hacc(b, v1); hacc(acc, v2); hacc(b, v3);
        hacc(acc, v4); hacc(b, v5); hacc(acc, v6); hacc(b, v7);
    }
    for (; k < cnt; k++) {
        int i0 = g_srcs[s0 + k];
        hacc(acc, __ldg(base + i0 * 5 + c));
    }
    #pragma unroll
    for (int j = 0; j < 8; j++) acc[j] += b[j];
}

// hop 1: z1 = dinv^2 * gather(z0), fp16 out
__global__ void k_gather1() {
    int t = blockIdx.x * blockDim.x + threadIdx.x;
    if (t >= NROW * 5) return;
    int node = t / 5, c = t % 5;
    float acc[8];
    gather8(acc, node, c, g_z0);
    float d = g_dinv[node];
    float s = d * d;
    uint4 o;
    *(__half2*)&o.x = __floats2half2_rn(acc[0] * s, acc[1] * s);
    *(__half2*)&o.y = __floats2half2_rn(acc[2] * s, acc[3] * s);
    *(__half2*)&o.z = __floats2half2_rn(acc[4] * s, acc[5] * s);
    *(__half2*)&o.w = __floats2half2_rn(acc[6] * s, acc[7] * s);
    ((uint4*)g_z1)[t] = o;
}

// hop 2 fused with bias + log_softmax. Block: 320 threads = 64 rows x 5 chunks.
__global__ __launch_bounds__(320) void k_gather2_lsm(float* __restrict__ out,
                                                     const float* __restrict__ bias) {
    __shared__ float vals[64 * 41];
    __shared__ float lse[64];
    int t = threadIdx.x;
    int r = t / 5, c = t % 5;
    int node = blockIdx.x * 64 + r;
    bool active = (node < NROW);

    if (active) {
        float acc[8];
        gather8(acc, node, c, g_z1);
        float d = g_dinv[node];
        #pragma unroll
        for (int j = 0; j < 8; j++)
            vals[r * 41 + c * 8 + j] = acc[j] * d + __ldg(&bias[c * 8 + j]);
    }
    __syncthreads();

    if (t < 64 && blockIdx.x * 64 + t < NROW) {
        const float* v = vals + t * 41;
        float m = v[0];
        #pragma unroll
        for (int j = 1; j < OUT_CH; j++) m = fmaxf(m, v[j]);
        float s = 0.f;
        #pragma unroll
        for (int j = 0; j < OUT_CH; j++) s += __expf(v[j] - m);
        lse[t] = m + __logf(s);
    }
    __syncthreads();

    if (active) {
        float l = lse[r];
        float4 o0, o1;
        const float* v = vals + r * 41 + c * 8;
        o0.x = v[0] - l; o0.y = v[1] - l; o0.z = v[2] - l; o0.w = v[3] - l;
        o1.x = v[4] - l; o1.y = v[5] - l; o1.z = v[6] - l; o1.w = v[7] - l;
        float4* op = (float4*)(out + (size_t)node * OUT_CH + c * 8);
        op[0] = o0; op[1] = o1;
    }
}

// ---------------------------------------------------------------------------
extern "C" void kernel_launch(void* const* d_in, const int* in_sizes, int n_in,
                              void* d_out, int out_size) {
    const float* x  = (const float*)d_in[0];
    const int*   ei = (const int*)d_in[1];    // int32 (JAX default x64 disabled)
    const float* W  = (const float*)d_in[2];
    const float* b  = (const float*)d_in[3];
    float*       out = (float*)d_out;

    const int T = 256;
    const int gC = (NED / 8 + T - 1) / T;            // 1563
    const int gG = (NROW * 5 + T - 1) / T;           // 1954
    const int gF = (NROW + 63) / 64;                 // 1563

    k_count      <<<gC, T>>>(ei);
    k_scan_nodes <<<NBLK, 256>>>();
    k_finalize   <<<NBLK, 256>>>();
    k_fill_gemm  <<<GEMM_BLOCKS + FILL_BLOCKS, FG_T>>>(x, W, ei);
    k_gather1    <<<gG, T>>>();
    k_gather2_lsm<<<gF, 320>>>(out, b);
}

// round 16
// speedup vs baseline: 1.0172x; 1.0020x over previous
#include <cuda_runtime.h>
#include <cuda_fp16.h>
#include <math.h>

#define NROW   100000
#define IN_CH  128
#define OUT_CH 40
#define NED    3200000
#define NBLK   ((NROW + 255) / 256)   // 391 scan blocks

// Row stride for z buffers: 24 half2 = 96 B (32B-aligned rows; 20 half2 used,
// 2 half2 pad). Every gathered 80B row = exactly 3 L2 sectors.
#define ZSTR   24                     // half2 per row
#define ZSTR4  6                      // uint4 per row

// Scratch (static device globals; BSS-zeroed at load)
__device__ __half2 g_z0[NROW * ZSTR]; // (xW)*dinv, fp16, 96 B/row (9.6 MB)
__device__ __half2 g_z1[NROW * ZSTR]; // after hop 1, fp16 (9.6 MB)
__device__ float   g_dinv[NROW];
__device__ int     g_degi[NROW];     // edge-only in-degree; re-zeroed each run
__device__ int     g_cnt[NROW];      // stable copy of edge counts
__device__ int     g_start[NROW];    // CSC row starts
__device__ int     g_cursor[NROW];
__device__ int     g_srcs[NED];      // CSC source indices (12.8 MB)
__device__ int     g_bsum[NBLK];

// ---------------------------------------------------------------------------
// count in-degree, 4 edges per thread (int4). g_degi zero on entry
// (BSS first call; k_finalize re-zeroes every run).
__global__ void k_count(const int* __restrict__ ei) {
    int t = blockIdx.x * blockDim.x + threadIdx.x;
    if (t >= NED / 4) return;
    int4 c4 = __ldg((const int4*)(ei + NED) + t);
    int c;
    c = c4.x; if ((unsigned)c >= NROW) c = 0; atomicAdd(&g_degi[c], 1);
    c = c4.y; if ((unsigned)c >= NROW) c = 0; atomicAdd(&g_degi[c], 1);
    c = c4.z; if ((unsigned)c >= NROW) c = 0; atomicAdd(&g_degi[c], 1);
    c = c4.w; if ((unsigned)c >= NROW) c = 0; atomicAdd(&g_degi[c], 1);
}

// ---------------------------------------------------------------------------
// Block-level exclusive scan over edge counts; per-block totals to g_bsum.
__global__ void k_scan_nodes() {
    __shared__ int sh[256];
    int tid = threadIdx.x;
    int i = blockIdx.x * 256 + tid;
    int c = (i < NROW) ? g_degi[i] : 0;
    sh[tid] = c;
    __syncthreads();
    #pragma unroll
    for (int off = 1; off < 256; off <<= 1) {
        int t = (tid >= off) ? sh[tid - off] : 0;
        __syncthreads();
        sh[tid] += t;
        __syncthreads();
    }
    if (i < NROW) g_start[i] = sh[tid] - c;
    if (tid == 255) g_bsum[blockIdx.x] = sh[tid];
}

// finalize: block offset = reduce(bsum[0..bid)), offsets, cursors, dinv,
// counts snapshot, degi re-zero.
__global__ void k_finalize() {
    __shared__ int red[256];
    int bid = blockIdx.x;
    int tid = threadIdx.x;
    int s = 0;
    for (int j = tid; j < bid; j += 256) s += g_bsum[j];
    red[tid] = s;
    __syncthreads();
    #pragma unroll
    for (int off = 128; off > 0; off >>= 1) {
        if (tid < off) red[tid] += red[tid + off];
        __syncthreads();
    }
    int boff = red[0];

    int i = bid * 256 + tid;
    if (i < NROW) {
        int st = g_start[i] + boff;
        g_start[i]  = st;
        g_cursor[i] = st;
        int c = g_degi[i];
        g_cnt[i]  = c;
        g_dinv[i] = rsqrtf((float)(c + 1));   // deg incl. self-loop
        g_degi[i] = 0;                        // restore invariant for next run
    }
}

// ---------------------------------------------------------------------------
// Fused kernel: HMMA GEMM blocks + CSC-fill blocks (R10 winner; only the
// z0 row stride changed 20 -> 24 half2).
#define GEMM_BLOCKS 782                 // ceil(100000 / 128), 8 warps x 16 rows
#define FILL_BLOCKS 3125                // NED / (256*4)
#define FG_T        256
#define WSTRIDE     136                 // half-stride of transposed W (bank-safe)

__global__ __launch_bounds__(FG_T)
void k_fill_gemm(const float* __restrict__ x,
                 const float* __restrict__ W,
                 const int* __restrict__ ei) {
    __shared__ __half wsmT[OUT_CH * WSTRIDE];   // W^T fp16, [n][k], 10.9 KB

    if (blockIdx.x < GEMM_BLOCKS) {
        for (int i = threadIdx.x; i < IN_CH * OUT_CH; i += FG_T) {
            int k = i / OUT_CH, n = i % OUT_CH;
            wsmT[n * WSTRIDE + k] = __float2half_rn(W[i]);
        }
        __syncthreads();

        int warp = threadIdx.x >> 5, lane = threadIdx.x & 31;
        int r0 = (blockIdx.x * 8 + warp) * 16;
        if (r0 >= NROW) return;                  // 100000 % 16 == 0
        int qrow = lane >> 2;                    // 0..7
        int qcol = (lane & 3) * 2;               // 0,2,4,6

        float c[5][4];
        #pragma unroll
        for (int nt = 0; nt < 5; nt++)
            c[nt][0] = c[nt][1] = c[nt][2] = c[nt][3] = 0.f;

        const float* xr0 = x + (size_t)(r0 + qrow) * IN_CH + qcol;
        const float* xr8 = xr0 + 8 * IN_CH;

        #pragma unroll
        for (int ks = 0; ks < 8; ks++) {
            int k0 = ks * 16;
            float2 f0 = *(const float2*)(xr0 + k0);
            float2 f1 = *(const float2*)(xr8 + k0);
            float2 f2 = *(const float2*)(xr0 + k0 + 8);
            float2 f3 = *(const float2*)(xr8 + k0 + 8);
            __half2 h0 = __floats2half2_rn(f0.x, f0.y);
            __half2 h1 = __floats2half2_rn(f1.x, f1.y);
            __half2 h2 = __floats2half2_rn(f2.x, f2.y);
            __half2 h3 = __floats2half2_rn(f3.x, f3.y);
            unsigned A0 = *(unsigned*)&h0, A1 = *(unsigned*)&h1;
            unsigned A2 = *(unsigned*)&h2, A3 = *(unsigned*)&h3;

            #pragma unroll
            for (int nt = 0; nt < 5; nt++) {
                int n = nt * 8 + qrow;
                unsigned B0 = *(const unsigned*)&wsmT[n * WSTRIDE + k0 + qcol];
                unsigned B1 = *(const unsigned*)&wsmT[n * WSTRIDE + k0 + qcol + 8];
                asm volatile(
                    "mma.sync.aligned.m16n8k16.row.col.f32.f16.f16.f32 "
                    "{%0,%1,%2,%3}, {%4,%5,%6,%7}, {%8,%9}, {%0,%1,%2,%3};\n"
                    : "+f"(c[nt][0]), "+f"(c[nt][1]), "+f"(c[nt][2]), "+f"(c[nt][3])
                    : "r"(A0), "r"(A1), "r"(A2), "r"(A3), "r"(B0), "r"(B1));
            }
        }

        int row0 = r0 + qrow, row8 = row0 + 8;
        float d0 = g_dinv[row0], d8 = g_dinv[row8];
        #pragma unroll
        for (int nt = 0; nt < 5; nt++) {
            int cidx = nt * 4 + (qcol >> 1);
            g_z0[row0 * ZSTR + cidx] = __floats2half2_rn(c[nt][0] * d0, c[nt][1] * d0);
            g_z0[row8 * ZSTR + cidx] = __floats2half2_rn(c[nt][2] * d8, c[nt][3] * d8);
        }
    } else {
        // ---- CSC fill branch: 4 edges per thread ----
        int t = (blockIdx.x - GEMM_BLOCKS) * FG_T + threadIdx.x;
        if (t >= NED / 4) return;
        int4 r4 = __ldg((const int4*)ei + t);
        int4 c4 = __ldg((const int4*)(ei + NED) + t);
        int r, c, slot;
        r = r4.x; c = c4.x;
        if ((unsigned)r >= NROW) r = 0;
        if ((unsigned)c >= NROW) c = 0;
        slot = atomicAdd(&g_cursor[c], 1); g_srcs[slot] = r;
        r = r4.y; c = c4.y;
        if ((unsigned)r >= NROW) r = 0;
        if ((unsigned)c >= NROW) c = 0;
        slot = atomicAdd(&g_cursor[c], 1); g_srcs[slot] = r;
        r = r4.z; c = c4.z;
        if ((unsigned)r >= NROW) r = 0;
        if ((unsigned)c >= NROW) c = 0;
        slot = atomicAdd(&g_cursor[c], 1); g_srcs[slot] = r;
        r = r4.w; c = c4.w;
        if ((unsigned)r >= NROW) r = 0;
        if ((unsigned)c >= NROW) c = 0;
        slot = atomicAdd(&g_cursor[c], 1); g_srcs[slot] = r;
    }
}

// ---------------------------------------------------------------------------
// fp16 gather core: thread = (node, chunk c in 0..4), chunk = 8 channels.
// Rows are 96B-aligned: each gathered row = exactly 3 L2 sectors.
__device__ __forceinline__ void hacc(float* a, uint4 v) {
    float2 f;
    f = __half22float2(*(__half2*)&v.x); a[0] += f.x; a[1] += f.y;
    f = __half22float2(*(__half2*)&v.y); a[2] += f.x; a[3] += f.y;
    f = __half22float2(*(__half2*)&v.z); a[4] += f.x; a[5] += f.y;
    f = __half22float2(*(__half2*)&v.w); a[6] += f.x; a[7] += f.y;
}

__device__ __forceinline__ void gather8(float* acc, int node, int c,
                                        const __half2* __restrict__ src) {
    const uint4* base = (const uint4*)src;     // ZSTR4 uint4 per row
    float b[8];
    #pragma unroll
    for (int j = 0; j < 8; j++) { acc[j] = 0.f; b[j] = 0.f; }

    uint4 self = __ldg(base + node * ZSTR4 + c);
    hacc(acc, self);

    int s0  = g_start[node];
    int cnt = g_cnt[node];                     // edge-only count
    int k = 0;
    for (; k + 8 <= cnt; k += 8) {
        int i0 = g_srcs[s0 + k + 0];
        int i1 = g_srcs[s0 + k + 1];
        int i2 = g_srcs[s0 + k + 2];
        int i3 = g_srcs[s0 + k + 3];
        int i4 = g_srcs[s0 + k + 4];
        int i5 = g_srcs[s0 + k + 5];
        int i6 = g_srcs[s0 + k + 6];
        int i7 = g_srcs[s0 + k + 7];
        uint4 v0 = __ldg(base + i0 * ZSTR4 + c);
        uint4 v1 = __ldg(base + i1 * ZSTR4 + c);
        uint4 v2 = __ldg(base + i2 * ZSTR4 + c);
        uint4 v3 = __ldg(base + i3 * ZSTR4 + c);
        uint4 v4 = __ldg(base + i4 * ZSTR4 + c);
        uint4 v5 = __ldg(base + i5 * ZSTR4 + c);
        uint4 v6 = __ldg(base + i6 * ZSTR4 + c);
        uint4 v7 = __ldg(base + i7 * ZSTR4 + c);
        hacc(acc, v0); hacc(b, v1); hacc(acc, v2); hacc(b, v3);
        hacc(acc, v4); hacc(b, v5); hacc(acc, v6); hacc(b, v7);
    }
    for (; k < cnt; k++) {
        int i0 = g_srcs[s0 + k];
        hacc(acc, __ldg(base + i0 * ZSTR4 + c));
    }
    #pragma unroll
    for (int j = 0; j < 8; j++) acc[j] += b[j];
}

// hop 1: z1 = dinv^2 * gather(z0), fp16 out
__global__ void k_gather1() {
    int t = blockIdx.x * blockDim.x + threadIdx.x;
    if (t >= NROW * 5) return;
    int node = t / 5, c = t % 5;
    float acc[8];
    gather8(acc, node, c, g_z0);
    float d = g_dinv[node];
    float s = d * d;
    uint4 o;
    *(__half2*)&o.x = __floats2half2_rn(acc[0] * s, acc[1] * s);
    *(__half2*)&o.y = __floats2half2_rn(acc[2] * s, acc[3] * s);
    *(__half2*)&o.z = __floats2half2_rn(acc[4] * s, acc[5] * s);
    *(__half2*)&o.w = __floats2half2_rn(acc[6] * s, acc[7] * s);
    ((uint4*)g_z1)[node * ZSTR4 + c] = o;
}

// hop 2 fused with bias + log_softmax. Block: 320 threads = 64 rows x 5 chunks.
__global__ __launch_bounds__(320) void k_gather2_lsm(float* __restrict__ out,
                                                     const float* __restrict__ bias) {
    __shared__ float vals[64 * 41];
    __shared__ float lse[64];
    int t = threadIdx.x;
    int r = t / 5, c = t % 5;
    int node = blockIdx.x * 64 + r;
    bool active = (node < NROW);

    if (active) {
        float acc[8];
        gather8(acc, node, c, g_z1);
        float d = g_dinv[node];
        #pragma unroll
        for (int j = 0; j < 8; j++)
            vals[r * 41 + c * 8 + j] = acc[j] * d + __ldg(&bias[c * 8 + j]);
    }
    __syncthreads();

    if (t < 64 && blockIdx.x * 64 + t < NROW) {
        const float* v = vals + t * 41;
        float m = v[0];
        #pragma unroll
        for (int j = 1; j < OUT_CH; j++) m = fmaxf(m, v[j]);
        float s = 0.f;
        #pragma unroll
        for (int j = 0; j < OUT_CH; j++) s += __expf(v[j] - m);
        lse[t] = m + __logf(s);
    }
    __syncthreads();

    if (active) {
        float l = lse[r];
        float4 o0, o1;
        const float* v = vals + r * 41 + c * 8;
        o0.x = v[0] - l; o0.y = v[1] - l; o0.z = v[2] - l; o0.w = v[3] - l;
        o1.x = v[4] - l; o1.y = v[5] - l; o1.z = v[6] - l; o1.w = v[7] - l;
        float4* op = (float4*)(out + (size_t)node * OUT_CH + c * 8);
        op[0] = o0; op[1] = o1;
    }
}

// ---------------------------------------------------------------------------
extern "C" void kernel_launch(void* const* d_in, const int* in_sizes, int n_in,
                              void* d_out, int out_size) {
    const float* x  = (const float*)d_in[0];
    const int*   ei = (const int*)d_in[1];    // int32 (JAX default x64 disabled)
    const float* W  = (const float*)d_in[2];
    const float* b  = (const float*)d_in[3];
    float*       out = (float*)d_out;

    const int T = 256;
    const int gC = (NED / 4 + T - 1) / T;            // 3125
    const int gG = (NROW * 5 + T - 1) / T;           // 1954
    const int gF = (NROW + 63) / 64;                 // 1563

    k_count      <<<gC, T>>>(ei);
    k_scan_nodes <<<NBLK, 256>>>();
    k_finalize   <<<NBLK, 256>>>();
    k_fill_gemm  <<<GEMM_BLOCKS + FILL_BLOCKS, FG_T>>>(x, W, ei);
    k_gather1    <<<gG, T>>>();
    k_gather2_lsm<<<gF, 320>>>(out, b);
}

// round 17
// speedup vs baseline: 1.0808x; 1.0625x over previous
#include <cuda_runtime.h>
#include <cuda_fp16.h>
#include <math.h>

#define NROW   100000
#define IN_CH  128
#define OUT_CH 40
#define NED    3200000
#define NBLK   ((NROW + 255) / 256)   // 391 scan blocks

// Scratch (static device globals; BSS-zeroed at load)
__device__ __half2 g_z0[NROW * 20];  // (xW)*dinv, fp16, 80 B/row (8 MB)
__device__ __half2 g_z1[NROW * 20];  // after hop 1, fp16 (8 MB)
__device__ float   g_dinv[NROW];
__device__ int     g_degi[NROW];     // edge-only in-degree; re-zeroed each run
__device__ int     g_cnt[NROW];      // stable copy of edge counts
__device__ int     g_start[NROW];    // CSC row starts
__device__ int     g_cursor[NROW];
__device__ int     g_srcs[NED];      // CSC source indices (12.8 MB)
__device__ int     g_bsum[NBLK];

// ---------------------------------------------------------------------------
// count in-degree, 4 edges per thread (int4). g_degi zero on entry
// (BSS first call; k_finalize re-zeroes every run).
__global__ void k_count(const int* __restrict__ ei) {
    int t = blockIdx.x * blockDim.x + threadIdx.x;
    if (t >= NED / 4) return;
    int4 c4 = __ldg((const int4*)(ei + NED) + t);
    int c;
    c = c4.x; if ((unsigned)c >= NROW) c = 0; atomicAdd(&g_degi[c], 1);
    c = c4.y; if ((unsigned)c >= NROW) c = 0; atomicAdd(&g_degi[c], 1);
    c = c4.z; if ((unsigned)c >= NROW) c = 0; atomicAdd(&g_degi[c], 1);
    c = c4.w; if ((unsigned)c >= NROW) c = 0; atomicAdd(&g_degi[c], 1);
}

// ---------------------------------------------------------------------------
// Block-level exclusive scan over edge counts; per-block totals to g_bsum.
__global__ void k_scan_nodes() {
    __shared__ int sh[256];
    int tid = threadIdx.x;
    int i = blockIdx.x * 256 + tid;
    int c = (i < NROW) ? g_degi[i] : 0;
    sh[tid] = c;
    __syncthreads();
    #pragma unroll
    for (int off = 1; off < 256; off <<= 1) {
        int t = (tid >= off) ? sh[tid - off] : 0;
        __syncthreads();
        sh[tid] += t;
        __syncthreads();
    }
    if (i < NROW) g_start[i] = sh[tid] - c;
    if (tid == 255) g_bsum[blockIdx.x] = sh[tid];
}

// finalize: block offset = reduce(bsum[0..bid)), offsets, cursors, dinv,
// counts snapshot, degi re-zero.
__global__ void k_finalize() {
    __shared__ int red[256];
    int bid = blockIdx.x;
    int tid = threadIdx.x;
    int s = 0;
    for (int j = tid; j < bid; j += 256) s += g_bsum[j];
    red[tid] = s;
    __syncthreads();
    #pragma unroll
    for (int off = 128; off > 0; off >>= 1) {
        if (tid < off) red[tid] += red[tid + off];
        __syncthreads();
    }
    int boff = red[0];

    int i = bid * 256 + tid;
    if (i < NROW) {
        int st = g_start[i] + boff;
        g_start[i]  = st;
        g_cursor[i] = st;
        int c = g_degi[i];
        g_cnt[i]  = c;
        g_dinv[i] = rsqrtf((float)(c + 1));   // deg incl. self-loop
        g_degi[i] = 0;                        // restore invariant for next run
    }
}

// ---------------------------------------------------------------------------
// Fused kernel: HMMA GEMM + CSC fill with INTERLEAVED block roles.
// bid % 5 == 0 -> GEMM (782 blocks: bids 0,5,...,3905); else fill (3125).
// Each residency wave is ~20% GEMM / 80% fill, so GEMM's tensor/L1 work
// executes inside fill's idle issue slots instead of in separate waves.
#define GEMM_BLOCKS 782                 // ceil(100000 / 128), 8 warps x 16 rows
#define FILL_BLOCKS 3125                // NED / (256*4)
#define FG_T        256
#define WSTRIDE     136                 // half-stride of transposed W (bank-safe)

__global__ __launch_bounds__(FG_T)
void k_fill_gemm(const float* __restrict__ x,
                 const float* __restrict__ W,
                 const int* __restrict__ ei) {
    __shared__ __half wsmT[OUT_CH * WSTRIDE];   // W^T fp16, [n][k], 10.9 KB

    int bid = blockIdx.x;
    if (bid % 5 == 0) {
        // ---- GEMM branch (gemm block index = bid/5, in [0,782)) ----
        int gb = bid / 5;
        for (int i = threadIdx.x; i < IN_CH * OUT_CH; i += FG_T) {
            int k = i / OUT_CH, n = i % OUT_CH;
            wsmT[n * WSTRIDE + k] = __float2half_rn(W[i]);
        }
        __syncthreads();

        int warp = threadIdx.x >> 5, lane = threadIdx.x & 31;
        int r0 = (gb * 8 + warp) * 16;
        if (r0 >= NROW) return;                  // 100000 % 16 == 0
        int qrow = lane >> 2;                    // 0..7
        int qcol = (lane & 3) * 2;               // 0,2,4,6

        float c[5][4];
        #pragma unroll
        for (int nt = 0; nt < 5; nt++)
            c[nt][0] = c[nt][1] = c[nt][2] = c[nt][3] = 0.f;

        const float* xr0 = x + (size_t)(r0 + qrow) * IN_CH + qcol;
        const float* xr8 = xr0 + 8 * IN_CH;

        #pragma unroll
        for (int ks = 0; ks < 8; ks++) {
            int k0 = ks * 16;
            float2 f0 = *(const float2*)(xr0 + k0);
            float2 f1 = *(const float2*)(xr8 + k0);
            float2 f2 = *(const float2*)(xr0 + k0 + 8);
            float2 f3 = *(const float2*)(xr8 + k0 + 8);
            __half2 h0 = __floats2half2_rn(f0.x, f0.y);
            __half2 h1 = __floats2half2_rn(f1.x, f1.y);
            __half2 h2 = __floats2half2_rn(f2.x, f2.y);
            __half2 h3 = __floats2half2_rn(f3.x, f3.y);
            unsigned A0 = *(unsigned*)&h0, A1 = *(unsigned*)&h1;
            unsigned A2 = *(unsigned*)&h2, A3 = *(unsigned*)&h3;

            #pragma unroll
            for (int nt = 0; nt < 5; nt++) {
                int n = nt * 8 + qrow;
                unsigned B0 = *(const unsigned*)&wsmT[n * WSTRIDE + k0 + qcol];
                unsigned B1 = *(const unsigned*)&wsmT[n * WSTRIDE + k0 + qcol + 8];
                asm volatile(
                    "mma.sync.aligned.m16n8k16.row.col.f32.f16.f16.f32 "
                    "{%0,%1,%2,%3}, {%4,%5,%6,%7}, {%8,%9}, {%0,%1,%2,%3};\n"
                    : "+f"(c[nt][0]), "+f"(c[nt][1]), "+f"(c[nt][2]), "+f"(c[nt][3])
                    : "r"(A0), "r"(A1), "r"(A2), "r"(A3), "r"(B0), "r"(B1));
            }
        }

        int row0 = r0 + qrow, row8 = row0 + 8;
        float d0 = g_dinv[row0], d8 = g_dinv[row8];
        #pragma unroll
        for (int nt = 0; nt < 5; nt++) {
            int cidx = nt * 4 + (qcol >> 1);
            g_z0[row0 * 20 + cidx] = __floats2half2_rn(c[nt][0] * d0, c[nt][1] * d0);
            g_z0[row8 * 20 + cidx] = __floats2half2_rn(c[nt][2] * d8, c[nt][3] * d8);
        }
    } else {
        // ---- CSC fill branch (fill block index in [0,3125)) ----
        int fb = (bid / 5) * 4 + (bid % 5) - 1;
        int t = fb * FG_T + threadIdx.x;
        if (t >= NED / 4) return;
        int4 r4 = __ldg((const int4*)ei + t);
        int4 c4 = __ldg((const int4*)(ei + NED) + t);
        int r, c, slot;
        r = r4.x; c = c4.x;
        if ((unsigned)r >= NROW) r = 0;
        if ((unsigned)c >= NROW) c = 0;
        slot = atomicAdd(&g_cursor[c], 1); g_srcs[slot] = r;
        r = r4.y; c = c4.y;
        if ((unsigned)r >= NROW) r = 0;
        if ((unsigned)c >= NROW) c = 0;
        slot = atomicAdd(&g_cursor[c], 1); g_srcs[slot] = r;
        r = r4.z; c = c4.z;
        if ((unsigned)r >= NROW) r = 0;
        if ((unsigned)c >= NROW) c = 0;
        slot = atomicAdd(&g_cursor[c], 1); g_srcs[slot] = r;
        r = r4.w; c = c4.w;
        if ((unsigned)r >= NROW) r = 0;
        if ((unsigned)c >= NROW) c = 0;
        slot = atomicAdd(&g_cursor[c], 1); g_srcs[slot] = r;
    }
}

// ---------------------------------------------------------------------------
// fp16 gather core: thread = (node, chunk c in 0..4), chunk = 8 channels.
__device__ __forceinline__ void hacc(float* a, uint4 v) {
    float2 f;
    f = __half22float2(*(__half2*)&v.x); a[0] += f.x; a[1] += f.y;
    f = __half22float2(*(__half2*)&v.y); a[2] += f.x; a[3] += f.y;
    f = __half22float2(*(__half2*)&v.z); a[4] += f.x; a[5] += f.y;
    f = __half22float2(*(__half2*)&v.w); a[6] += f.x; a[7] += f.y;
}

__device__ __forceinline__ void gather8(float* acc, int node, int c,
                                        const __half2* __restrict__ src) {
    const uint4* base = (const uint4*)src;     // 5 uint4 per row
    float b[8];
    #pragma unroll
    for (int j = 0; j < 8; j++) { acc[j] = 0.f; b[j] = 0.f; }

    uint4 self = __ldg(base + node * 5 + c);
    hacc(acc, self);

    int s0  = g_start[node];
    int cnt = g_cnt[node];                     // edge-only count
    int k = 0;
    for (; k + 8 <= cnt; k += 8) {
        int i0 = g_srcs[s0 + k + 0];
        int i1 = g_srcs[s0 + k + 1];
        int i2 = g_srcs[s0 + k + 2];
        int i3 = g_srcs[s0 + k + 3];
        int i4 = g_srcs[s0 + k + 4];
        int i5 = g_srcs[s0 + k + 5];
        int i6 = g_srcs[s0 + k + 6];
        int i7 = g_srcs[s0 + k + 7];
        uint4 v0 = __ldg(base + i0 * 5 + c);
        uint4 v1 = __ldg(base + i1 * 5 + c);
        uint4 v2 = __ldg(base + i2 * 5 + c);
        uint4 v3 = __ldg(base + i3 * 5 + c);
        uint4 v4 = __ldg(base + i4 * 5 + c);
        uint4 v5 = __ldg(base + i5 * 5 + c);
        uint4 v6 = __ldg(base + i6 * 5 + c);
        uint4 v7 = __ldg(base + i7 * 5 + c);
        hacc(acc, v0); hacc(b, v1); hacc(acc, v2); hacc(b, v3);
        hacc(acc, v4); hacc(b, v5); hacc(acc, v6); hacc(b, v7);
    }
    for (; k < cnt; k++) {
        int i0 = g_srcs[s0 + k];
        hacc(acc, __ldg(base + i0 * 5 + c));
    }
    #pragma unroll
    for (int j = 0; j < 8; j++) acc[j] += b[j];
}

// hop 1: z1 = dinv^2 * gather(z0), fp16 out
__global__ void k_gather1() {
    int t = blockIdx.x * blockDim.x + threadIdx.x;
    if (t >= NROW * 5) return;
    int node = t / 5, c = t % 5;
    float acc[8];
    gather8(acc, node, c, g_z0);
    float d = g_dinv[node];
    float s = d * d;
    uint4 o;
    *(__half2*)&o.x = __floats2half2_rn(acc[0] * s, acc[1] * s);
    *(__half2*)&o.y = __floats2half2_rn(acc[2] * s, acc[3] * s);
    *(__half2*)&o.z = __floats2half2_rn(acc[4] * s, acc[5] * s);
    *(__half2*)&o.w = __floats2half2_rn(acc[6] * s, acc[7] * s);
    ((uint4*)g_z1)[t] = o;
}

// hop 2 fused with bias + log_softmax. Block: 320 threads = 64 rows x 5 chunks.
__global__ __launch_bounds__(320) void k_gather2_lsm(float* __restrict__ out,
                                                     const float* __restrict__ bias) {
    __shared__ float vals[64 * 41];
    __shared__ float lse[64];
    int t = threadIdx.x;
    int r = t / 5, c = t % 5;
    int node = blockIdx.x * 64 + r;
    bool active = (node < NROW);

    if (active) {
        float acc[8];
        gather8(acc, node, c, g_z1);
        float d = g_dinv[node];
        #pragma unroll
        for (int j = 0; j < 8; j++)
            vals[r * 41 + c * 8 + j] = acc[j] * d + __ldg(&bias[c * 8 + j]);
    }
    __syncthreads();

    if (t < 64 && blockIdx.x * 64 + t < NROW) {
        const float* v = vals + t * 41;
        float m = v[0];
        #pragma unroll
        for (int j = 1; j < OUT_CH; j++) m = fmaxf(m, v[j]);
        float s = 0.f;
        #pragma unroll
        for (int j = 0; j < OUT_CH; j++) s += __expf(v[j] - m);
        lse[t] = m + __logf(s);
    }
    __syncthreads();

    if (active) {
        float l = lse[r];
        float4 o0, o1;
        const float* v = vals + r * 41 + c * 8;
        o0.x = v[0] - l; o0.y = v[1] - l; o0.z = v[2] - l; o0.w = v[3] - l;
        o1.x = v[4] - l; o1.y = v[5] - l; o1.z = v[6] - l; o1.w = v[7] - l;
        float4* op = (float4*)(out + (size_t)node * OUT_CH + c * 8);
        op[0] = o0; op[1] = o1;
    }
}

// ---------------------------------------------------------------------------
extern "C" void kernel_launch(void* const* d_in, const int* in_sizes, int n_in,
                              void* d_out, int out_size) {
    const float* x  = (const float*)d_in[0];
    const int*   ei = (const int*)d_in[1];    // int32 (JAX default x64 disabled)
    const float* W  = (const float*)d_in[2];
    const float* b  = (const float*)d_in[3];
    float*       out = (float*)d_out;

    const int T = 256;
    const int gC = (NED / 4 + T - 1) / T;            // 3125
    const int gG = (NROW * 5 + T - 1) / T;           // 1954
    const int gF = (NROW + 63) / 64;                 // 1563

    k_count      <<<gC, T>>>(ei);
    k_scan_nodes <<<NBLK, 256>>>();
    k_finalize   <<<NBLK, 256>>>();
    k_fill_gemm  <<<GEMM_BLOCKS + FILL_BLOCKS, FG_T>>>(x, W, ei);
    k_gather1    <<<gG, T>>>();
    k_gather2_lsm<<<gF, 320>>>(out, b);
}